// round 5
// baseline (speedup 1.0000x reference)
#include <cuda_runtime.h>
#include <math.h>

// Problem constants
#define Bsz   32
#define Tn    512
#define Jn    25
#define DENC  256
#define Hn    512
#define G4    2048      // 4*H
#define NB    128       // persistent recurrence grid (<= 148 SMs -> co-resident)

// ---------------- scratch (device globals; no allocations) ----------------
__device__ float g_enc [Bsz * Tn * DENC];                 // 16 MB
__device__ float g_xg  [2 * Tn * Bsz * G4];               // 268 MB  [d][t][b][4H]
__device__ float g_out0[Bsz * Tn * 2 * Hn];               // 67 MB   [b][t][2H]
__device__ float g_out1[Bsz * Tn * 2 * Hn];               // 67 MB
__device__ float g_h   [2 * Bsz * Hn];                    // [d][b][H]
__device__ float g_part[2 * 4 * G4 * Bsz];                // [d][chunk][g][b]
__device__ unsigned g_bar_cnt;                            // zero-init
__device__ unsigned g_bar_gen;

// ---------------- grid-wide barrier (all NB blocks resident) --------------
__device__ __forceinline__ void grid_sync() {
    __threadfence();
    __syncthreads();
    if (threadIdx.x == 0) {
        volatile unsigned* vg = &g_bar_gen;
        unsigned gen = *vg;
        if (atomicAdd(&g_bar_cnt, 1u) == NB - 1) {
            g_bar_cnt = 0;
            __threadfence();
            *vg = gen + 1;
        } else {
            while (*vg == gen) { __nanosleep(40); }
        }
    }
    __syncthreads();
    __threadfence();
}

// ---------------- zero the output buffers (padded positions must be 0) ----
__global__ void zero_kernel() {
    const int n4 = (Bsz * Tn * 2 * Hn) / 4;   // float4 count per buffer
    float4 z = make_float4(0.f, 0.f, 0.f, 0.f);
    for (int i = blockIdx.x * blockDim.x + threadIdx.x; i < n4;
         i += gridDim.x * blockDim.x) {
        reinterpret_cast<float4*>(g_out0)[i] = z;
        reinterpret_cast<float4*>(g_out1)[i] = z;
    }
}

// ---------------- encoder: relu(masked_xy @ W^T + b) ----------------------
// grid = B*T blocks, 256 threads (one output feature each)
__global__ void enc_kernel(const float* __restrict__ feats,
                           const float* __restrict__ W,
                           const float* __restrict__ bias) {
    __shared__ float xs[2 * Jn];
    const int bt  = blockIdx.x;
    const int tid = threadIdx.x;
    const float* f = feats + (size_t)bt * (Jn * 3);
    if (tid < Jn) {
        float c = (f[tid * 3 + 2] > 0.1f) ? 1.f : 0.f;
        xs[tid * 2 + 0] = f[tid * 3 + 0] * c;
        xs[tid * 2 + 1] = f[tid * 3 + 1] * c;
    }
    __syncthreads();
    const float* w = W + tid * (2 * Jn);
    float s = bias[tid];
#pragma unroll
    for (int k = 0; k < 2 * Jn; ++k) s += xs[k] * w[k];
    g_enc[(size_t)bt * DENC + tid] = fmaxf(s, 0.f);
}

// ---------------- input projection GEMM -----------------------------------
// C[d][t][b][g] = A[m=b*T+t, :K] . W[d][g, :K] + bias[d][g]
// A = g_enc (srcSel=0, K=256) or g_out0 (srcSel=1, K=1024)
// grid = (N/128=16, M/128=128, 2 dirs), 256 threads, 8x8 per-thread tile
__global__ void __launch_bounds__(256)
proj_gemm(int srcSel, int K, const float* __restrict__ W,
          const float* __restrict__ bias) {
    const float* A  = srcSel ? g_out0 : g_enc;
    const int d  = blockIdx.z;
    const float* Wd = W + (size_t)d * G4 * K;
    const float* bd = bias + d * G4;
    const int n0 = blockIdx.x * 128;
    const int m0 = blockIdx.y * 128;

    __shared__ float As[16][128];
    __shared__ float Bs[16][128];

    const int tid = threadIdx.x;
    const int tx = tid & 15;          // n sub-tile
    const int ty = tid >> 4;          // m sub-tile

    float acc[8][8];
#pragma unroll
    for (int i = 0; i < 8; ++i)
#pragma unroll
        for (int j = 0; j < 8; ++j) acc[i][j] = 0.f;

    for (int kt = 0; kt < K; kt += 16) {
#pragma unroll
        for (int r = 0; r < 2; ++r) {
            int f4  = tid + r * 256;          // 0..511
            int row = f4 >> 2;                // 0..127
            int kq  = (f4 & 3) << 2;          // 0,4,8,12
            float4 va = *reinterpret_cast<const float4*>(
                A + (size_t)(m0 + row) * K + kt + kq);
            As[kq + 0][row] = va.x; As[kq + 1][row] = va.y;
            As[kq + 2][row] = va.z; As[kq + 3][row] = va.w;
            float4 vb = *reinterpret_cast<const float4*>(
                Wd + (size_t)(n0 + row) * K + kt + kq);
            Bs[kq + 0][row] = vb.x; Bs[kq + 1][row] = vb.y;
            Bs[kq + 2][row] = vb.z; Bs[kq + 3][row] = vb.w;
        }
        __syncthreads();
#pragma unroll
        for (int kk = 0; kk < 16; ++kk) {
            float av[8], bv[8];
            *reinterpret_cast<float4*>(&av[0]) =
                *reinterpret_cast<const float4*>(&As[kk][ty * 8]);
            *reinterpret_cast<float4*>(&av[4]) =
                *reinterpret_cast<const float4*>(&As[kk][ty * 8 + 4]);
            *reinterpret_cast<float4*>(&bv[0]) =
                *reinterpret_cast<const float4*>(&Bs[kk][tx * 8]);
            *reinterpret_cast<float4*>(&bv[4]) =
                *reinterpret_cast<const float4*>(&Bs[kk][tx * 8 + 4]);
#pragma unroll
            for (int i = 0; i < 8; ++i)
#pragma unroll
                for (int j = 0; j < 8; ++j) acc[i][j] += av[i] * bv[j];
        }
        __syncthreads();
    }

    float br[8];
#pragma unroll
    for (int j = 0; j < 8; ++j) br[j] = bd[n0 + tx * 8 + j];

#pragma unroll
    for (int i = 0; i < 8; ++i) {
        int m  = m0 + ty * 8 + i;
        int t  = m & (Tn - 1);
        int bb = m >> 9;                 // / T
        float* cp = g_xg + (((size_t)d * Tn + t) * Bsz + bb) * G4 + n0 + tx * 8;
        float4 o0 = make_float4(acc[i][0] + br[0], acc[i][1] + br[1],
                                acc[i][2] + br[2], acc[i][3] + br[3]);
        float4 o1 = make_float4(acc[i][4] + br[4], acc[i][5] + br[5],
                                acc[i][6] + br[6], acc[i][7] + br[7]);
        *reinterpret_cast<float4*>(cp + 0) = o0;
        *reinterpret_cast<float4*>(cp + 4) = o1;
    }
}

// ---------------- persistent bidirectional LSTM recurrence ----------------
// NB=128 blocks. block -> (dir d, gate tile g0:128, K-chunk k0:128)
// phase 1: partial[d][chunk][g][b] = sum_{k in chunk} W_hh[d][g][k] * h[d][b][k]
// phase 2: thread (d,b,j) sums partials + xg, applies gates; c in register.
__global__ void __launch_bounds__(256, 1)
rec_kernel(const float* __restrict__ whh,      // [2][4H][H]
           const int*   __restrict__ lengths,
           int outSel) {
    float* out = outSel ? g_out1 : g_out0;
    const float* xg = g_xg;

    __shared__ float h_s[128][33];   // [kk][b], padded: conflict-free

    const int tid = threadIdx.x;
    const int bx  = blockIdx.x;
    const int d     = bx >> 6;
    const int rem   = bx & 63;
    const int g0    = (rem >> 2) * 128;
    const int chunk = rem & 3;
    const int k0    = chunk * 128;

    // ---- phase-2 identity: one thread per (dir, batch, hidden unit)
    const int gtid  = bx * 256 + tid;           // 0..32767
    const int p2_d  = gtid >> 14;
    const int p2_b  = (gtid >> 9) & 31;
    const int p2_j  = gtid & 511;
    const int p2_len = lengths[p2_b];
    float c_reg = 0.f;
    g_h[(p2_d * Bsz + p2_b) * Hn + p2_j] = 0.f;

    // ---- phase-1 per-thread tile: 4 gates x 4 batches
    const int tg = tid >> 3;        // 0..31 -> gates g0 + tg*4 + [0..3]
    const int tb = tid & 7;         // batches tb*4 + [0..3]
    const float* w0 = whh + ((size_t)d * G4 + (g0 + tg * 4 + 0)) * Hn + k0;
    const float* w1 = w0 + Hn;
    const float* w2 = w1 + Hn;
    const float* w3 = w2 + Hn;
    const int pbase = ((d * 4 + chunk) * G4 + (g0 + tg * 4)) * Bsz + tb * 4;

    grid_sync();   // h zeroed everywhere before first step

    for (int s = 0; s < Tn; ++s) {
        // stage h chunk: h_s[kk][b] = g_h[d][b][k0+kk]
        for (int i = tid; i < 32 * 128; i += 256) {
            int kk = i & 127, b = i >> 7;
            h_s[kk][b] = g_h[(d * Bsz + b) * Hn + k0 + kk];
        }
        __syncthreads();

        float acc[4][4];
#pragma unroll
        for (int gi = 0; gi < 4; ++gi)
#pragma unroll
            for (int bi = 0; bi < 4; ++bi) acc[gi][bi] = 0.f;

#pragma unroll 4
        for (int kk = 0; kk < 128; kk += 4) {
            float4 wv0 = *reinterpret_cast<const float4*>(w0 + kk);
            float4 wv1 = *reinterpret_cast<const float4*>(w1 + kk);
            float4 wv2 = *reinterpret_cast<const float4*>(w2 + kk);
            float4 wv3 = *reinterpret_cast<const float4*>(w3 + kk);
            float wa0[4] = {wv0.x, wv0.y, wv0.z, wv0.w};
            float wa1[4] = {wv1.x, wv1.y, wv1.z, wv1.w};
            float wa2[4] = {wv2.x, wv2.y, wv2.z, wv2.w};
            float wa3[4] = {wv3.x, wv3.y, wv3.z, wv3.w};
#pragma unroll
            for (int sk = 0; sk < 4; ++sk) {
                float hb0 = h_s[kk + sk][tb * 4 + 0];
                float hb1 = h_s[kk + sk][tb * 4 + 1];
                float hb2 = h_s[kk + sk][tb * 4 + 2];
                float hb3 = h_s[kk + sk][tb * 4 + 3];
                acc[0][0] += wa0[sk] * hb0; acc[0][1] += wa0[sk] * hb1;
                acc[0][2] += wa0[sk] * hb2; acc[0][3] += wa0[sk] * hb3;
                acc[1][0] += wa1[sk] * hb0; acc[1][1] += wa1[sk] * hb1;
                acc[1][2] += wa1[sk] * hb2; acc[1][3] += wa1[sk] * hb3;
                acc[2][0] += wa2[sk] * hb0; acc[2][1] += wa2[sk] * hb1;
                acc[2][2] += wa2[sk] * hb2; acc[2][3] += wa2[sk] * hb3;
                acc[3][0] += wa3[sk] * hb0; acc[3][1] += wa3[sk] * hb1;
                acc[3][2] += wa3[sk] * hb2; acc[3][3] += wa3[sk] * hb3;
            }
        }
#pragma unroll
        for (int gi = 0; gi < 4; ++gi) {
            float4 v = make_float4(acc[gi][0], acc[gi][1], acc[gi][2], acc[gi][3]);
            *reinterpret_cast<float4*>(&g_part[pbase + gi * Bsz]) = v;
        }

        grid_sync();   // partials visible everywhere

        // ---- phase 2: gate math for this thread's (d,b,j)
        if (s < p2_len) {
            const int t = p2_d ? (p2_len - 1 - s) : s;
            const float* xr =
                xg + (((size_t)p2_d * Tn + t) * Bsz + p2_b) * G4 + p2_j;
            float gv[4];
#pragma unroll
            for (int q = 0; q < 4; ++q) {
                float v = xr[q * Hn];
                int gidx = q * Hn + p2_j;
#pragma unroll
                for (int ch = 0; ch < 4; ++ch)
                    v += g_part[((p2_d * 4 + ch) * G4 + gidx) * Bsz + p2_b];
                gv[q] = v;
            }
            float ig = 1.f / (1.f + __expf(-gv[0]));
            float fg = 1.f / (1.f + __expf(-gv[1]));
            float gg = tanhf(gv[2]);
            float og = 1.f / (1.f + __expf(-gv[3]));
            c_reg = fg * c_reg + ig * gg;
            float hn = og * tanhf(c_reg);
            g_h[(p2_d * Bsz + p2_b) * Hn + p2_j] = hn;
            out[((size_t)p2_b * Tn + t) * (2 * Hn) + p2_d * Hn + p2_j] = hn;
        }

        grid_sync();   // h update visible before next step's staging
    }
}

// ---------------- mean pooling over valid length --------------------------
__global__ void pool_kernel(const int* __restrict__ lengths,
                            float* __restrict__ out) {
    const int c = blockIdx.x * 256 + threadIdx.x;   // 0..1023
    const int b = blockIdx.y;
    const float* p = g_out1 + (size_t)b * Tn * (2 * Hn) + c;
    float s = 0.f;
    for (int t = 0; t < Tn; ++t) s += p[(size_t)t * (2 * Hn)];
    out[b * (2 * Hn) + c] = s / (float)lengths[b];
}

// ---------------- launch ---------------------------------------------------
extern "C" void kernel_launch(void* const* d_in, const int* in_sizes, int n_in,
                              void* d_out, int out_size) {
    const float* feats = (const float*)d_in[0];
    const int*   lens  = (const int*)  d_in[1];
    const float* encW  = (const float*)d_in[2];
    const float* encb  = (const float*)d_in[3];
    const float* wih0  = (const float*)d_in[4];
    const float* whh0  = (const float*)d_in[5];
    const float* b0    = (const float*)d_in[6];
    const float* wih1  = (const float*)d_in[7];
    const float* whh1  = (const float*)d_in[8];
    const float* b1    = (const float*)d_in[9];
    float* out = (float*)d_out;

    zero_kernel<<<2048, 256>>>();
    enc_kernel<<<Bsz * Tn, 256>>>(feats, encW, encb);

    // layer 0: project (K=256) then scan
    {
        dim3 grid(16, 128, 2);
        proj_gemm<<<grid, 256>>>(0, DENC, wih0, b0);
        rec_kernel<<<NB, 256>>>(whh0, lens, 0);
    }
    // layer 1: project (K=1024) then scan
    {
        dim3 grid(16, 128, 2);
        proj_gemm<<<grid, 256>>>(1, 2 * Hn, wih1, b1);
        rec_kernel<<<NB, 256>>>(whh1, lens, 1);
    }

    dim3 pg(4, Bsz);
    pool_kernel<<<pg, 256>>>(lens, out);
}

// round 6
// speedup vs baseline: 2.8289x; 2.8289x over previous
#include <cuda_runtime.h>
#include <math.h>

// Problem constants
#define Bsz   32
#define Tn    512
#define Jn    25
#define DENC  256
#define Hn    512
#define G4    2048      // 4*H
#define NB    128       // persistent recurrence grid (<= 148 SMs -> co-resident)

// ---------------- scratch (device globals; no allocations) ----------------
__device__ float    g_enc [Bsz * Tn * DENC];
__device__ float    g_xg  [2 * Tn * Bsz * G4];            // [d][t][b][4H]
__device__ float    g_out0[Bsz * Tn * 2 * Hn];            // [b][t][2H]
__device__ float    g_out1[Bsz * Tn * 2 * Hn];
__device__ unsigned g_h   [2][2 * Bsz * Hn];              // tf32 bits, double-buffered
__device__ unsigned g_bar_cnt;
__device__ unsigned g_bar_gen;

// ---------------- helpers --------------------------------------------------
__device__ __forceinline__ unsigned f2tf(float x) {
    unsigned u;
    asm("cvt.rna.tf32.f32 %0, %1;" : "=r"(u) : "f"(x));
    return u;
}

__device__ __forceinline__ void mma_tf32(float* c,
                                         unsigned a0, unsigned a1,
                                         unsigned a2, unsigned a3,
                                         unsigned b0, unsigned b1) {
    asm("mma.sync.aligned.m16n8k8.row.col.f32.tf32.tf32.f32 "
        "{%0,%1,%2,%3}, {%4,%5,%6,%7}, {%8,%9}, {%0,%1,%2,%3};"
        : "+f"(c[0]), "+f"(c[1]), "+f"(c[2]), "+f"(c[3])
        : "r"(a0), "r"(a1), "r"(a2), "r"(a3), "r"(b0), "r"(b1));
}

// ---------------- grid-wide barrier (all NB blocks resident) --------------
__device__ __forceinline__ void grid_sync() {
    __threadfence();
    __syncthreads();
    if (threadIdx.x == 0) {
        volatile unsigned* vg = &g_bar_gen;
        unsigned gen = *vg;
        if (atomicAdd(&g_bar_cnt, 1u) == NB - 1) {
            g_bar_cnt = 0;
            __threadfence();
            *vg = gen + 1;
        } else {
            while (*vg == gen) { __nanosleep(40); }
        }
    }
    __syncthreads();
    __threadfence();
}

// ---------------- zero the output buffers ---------------------------------
__global__ void zero_kernel() {
    const int n4 = (Bsz * Tn * 2 * Hn) / 4;
    float4 z = make_float4(0.f, 0.f, 0.f, 0.f);
    for (int i = blockIdx.x * blockDim.x + threadIdx.x; i < n4;
         i += gridDim.x * blockDim.x) {
        reinterpret_cast<float4*>(g_out0)[i] = z;
        reinterpret_cast<float4*>(g_out1)[i] = z;
    }
}

// ---------------- encoder: relu(masked_xy @ W^T + b) ----------------------
__global__ void enc_kernel(const float* __restrict__ feats,
                           const float* __restrict__ W,
                           const float* __restrict__ bias) {
    __shared__ float xs[2 * Jn];
    const int bt  = blockIdx.x;
    const int tid = threadIdx.x;
    const float* f = feats + (size_t)bt * (Jn * 3);
    if (tid < Jn) {
        float c = (f[tid * 3 + 2] > 0.1f) ? 1.f : 0.f;
        xs[tid * 2 + 0] = f[tid * 3 + 0] * c;
        xs[tid * 2 + 1] = f[tid * 3 + 1] * c;
    }
    __syncthreads();
    const float* w = W + tid * (2 * Jn);
    float s = bias[tid];
#pragma unroll
    for (int k = 0; k < 2 * Jn; ++k) s += xs[k] * w[k];
    g_enc[(size_t)bt * DENC + tid] = fmaxf(s, 0.f);
}

// ---------------- input projection GEMM (tf32 tensor cores) ---------------
// out_xg[d][t][b][g] = A[m=b*T+t,:K] . W[d][g,:K] + bias[d][g]
// block 128x128, 8 warps (2m x 4n), warp 64x32, k-tile 16
__global__ void __launch_bounds__(256)
proj_gemm(int srcSel, int K, const float* __restrict__ W,
          const float* __restrict__ bias) {
    const float* A  = srcSel ? g_out0 : g_enc;
    const int d  = blockIdx.z;
    const float* Wd = W + (size_t)d * G4 * K;
    const float* bd = bias + d * G4;
    const int n0 = blockIdx.x * 128;
    const int m0 = blockIdx.y * 128;

    __shared__ unsigned As[128 * 20];   // [m][k], stride 20 -> conflict-free frags
    __shared__ unsigned Ws[128 * 20];   // [n][k]

    const int tid  = threadIdx.x;
    const int lane = tid & 31;
    const int wid  = tid >> 5;
    const int wm   = (wid >> 2) * 64;
    const int wn   = (wid & 3) * 32;

    float acc[4][4][4];
#pragma unroll
    for (int mt = 0; mt < 4; ++mt)
#pragma unroll
        for (int nt = 0; nt < 4; ++nt)
#pragma unroll
            for (int i = 0; i < 4; ++i) acc[mt][nt][i] = 0.f;

    const int r0  = tid >> 2;
    const int kq0 = (tid & 3) << 2;

    float4 pa0, pa1, pw0, pw1;
    pa0 = *reinterpret_cast<const float4*>(A  + (size_t)(m0 + r0)      * K + kq0);
    pa1 = *reinterpret_cast<const float4*>(A  + (size_t)(m0 + r0 + 64) * K + kq0);
    pw0 = *reinterpret_cast<const float4*>(Wd + (size_t)(n0 + r0)      * K + kq0);
    pw1 = *reinterpret_cast<const float4*>(Wd + (size_t)(n0 + r0 + 64) * K + kq0);

    for (int kt = 0; kt < K; kt += 16) {
        // convert + store staged tile
        {
            uint4 u;
            u.x = f2tf(pa0.x); u.y = f2tf(pa0.y); u.z = f2tf(pa0.z); u.w = f2tf(pa0.w);
            *reinterpret_cast<uint4*>(As + r0 * 20 + kq0) = u;
            u.x = f2tf(pa1.x); u.y = f2tf(pa1.y); u.z = f2tf(pa1.z); u.w = f2tf(pa1.w);
            *reinterpret_cast<uint4*>(As + (r0 + 64) * 20 + kq0) = u;
            u.x = f2tf(pw0.x); u.y = f2tf(pw0.y); u.z = f2tf(pw0.z); u.w = f2tf(pw0.w);
            *reinterpret_cast<uint4*>(Ws + r0 * 20 + kq0) = u;
            u.x = f2tf(pw1.x); u.y = f2tf(pw1.y); u.z = f2tf(pw1.z); u.w = f2tf(pw1.w);
            *reinterpret_cast<uint4*>(Ws + (r0 + 64) * 20 + kq0) = u;
        }
        __syncthreads();

        if (kt + 16 < K) {   // prefetch next tile while computing
            int kn = kt + 16;
            pa0 = *reinterpret_cast<const float4*>(A  + (size_t)(m0 + r0)      * K + kn + kq0);
            pa1 = *reinterpret_cast<const float4*>(A  + (size_t)(m0 + r0 + 64) * K + kn + kq0);
            pw0 = *reinterpret_cast<const float4*>(Wd + (size_t)(n0 + r0)      * K + kn + kq0);
            pw1 = *reinterpret_cast<const float4*>(Wd + (size_t)(n0 + r0 + 64) * K + kn + kq0);
        }

#pragma unroll
        for (int kk = 0; kk < 16; kk += 8) {
            unsigned af[4][4], bf[4][2];
#pragma unroll
            for (int mt = 0; mt < 4; ++mt) {
                const unsigned* p = As + (wm + mt * 16 + (lane >> 2)) * 20 + kk + (lane & 3);
                af[mt][0] = p[0];
                af[mt][1] = p[8 * 20];
                af[mt][2] = p[4];
                af[mt][3] = p[8 * 20 + 4];
            }
#pragma unroll
            for (int nt = 0; nt < 4; ++nt) {
                const unsigned* p = Ws + (wn + nt * 8 + (lane >> 2)) * 20 + kk + (lane & 3);
                bf[nt][0] = p[0];
                bf[nt][1] = p[4];
            }
#pragma unroll
            for (int mt = 0; mt < 4; ++mt)
#pragma unroll
                for (int nt = 0; nt < 4; ++nt)
                    mma_tf32(acc[mt][nt], af[mt][0], af[mt][1], af[mt][2], af[mt][3],
                             bf[nt][0], bf[nt][1]);
        }
        __syncthreads();
    }

    // epilogue: bias + scatter to g_xg
#pragma unroll
    for (int mt = 0; mt < 4; ++mt) {
        int mrow0 = m0 + wm + mt * 16 + (lane >> 2);
#pragma unroll
        for (int nt = 0; nt < 4; ++nt) {
            int n = n0 + wn + nt * 8 + (lane & 3) * 2;
            float bv0 = bd[n], bv1 = bd[n + 1];
#pragma unroll
            for (int h = 0; h < 2; ++h) {
                int m  = mrow0 + h * 8;
                int t  = m & (Tn - 1);
                int bb = m >> 9;
                float* cp = g_xg + (((size_t)d * Tn + t) * Bsz + bb) * G4 + n;
                float2 v = make_float2(acc[mt][nt][h * 2 + 0] + bv0,
                                       acc[mt][nt][h * 2 + 1] + bv1);
                *reinterpret_cast<float2*>(cp) = v;
            }
        }
    }
}

// ---------------- persistent bidirectional LSTM recurrence (tf32 MMA) -----
// 128 blocks: (d = bx>>6, j-slice j0 = (bx&63)*8). Per step:
//   C[batch 32][gate-row 32] = h[32,512] @ Whh_slice^T  via m16n8k8 tf32.
// warp = (mb: batch half, kc: K chunk 128). W frags stationary in registers.
// h double-buffered in gmem (tf32 bits) -> ONE grid_sync per step.
extern __shared__ unsigned sm_rec[];    // hs[32][516] + part[8][16][34]
#define REC_SMEM ((32 * 516 + 8 * 16 * 34) * 4)

__global__ void __launch_bounds__(256, 1)
rec_kernel(const float* __restrict__ whh,      // [2][4H][H]
           const int*   __restrict__ lengths,
           int outSel) {
    unsigned* hs  = sm_rec;                          // stride 516: conflict-free frags
    float*    part = (float*)(sm_rec + 32 * 516);    // [wid][m 16][n 34]
    float* out = outSel ? g_out1 : g_out0;
    const float* xg = g_xg;

    const int tid  = threadIdx.x;
    const int lane = tid & 31;
    const int wid  = tid >> 5;
    const int bx   = blockIdx.x;
    const int d    = bx >> 6;
    const int j0   = (bx & 63) << 3;
    const int mb   = wid & 1;
    const int kc   = wid >> 1;

    // stationary W fragments (B-side): b0,b1 per (ks, nt)
    unsigned wb0[16][4], wb1[16][4];
    {
        const float* wdb = whh + (size_t)d * G4 * Hn;
#pragma unroll
        for (int ks = 0; ks < 16; ++ks)
#pragma unroll
            for (int nt = 0; nt < 4; ++nt) {
                const float* wp = wdb + (size_t)(nt * Hn + j0 + (lane >> 2)) * Hn
                                  + kc * 128 + ks * 8 + (lane & 3);
                wb0[ks][nt] = f2tf(wp[0]);
                wb1[ks][nt] = f2tf(wp[4]);
            }
    }

    // phase-2 identity: one thread per (b, j) in this block's slice
    const int b2 = tid & 31;
    const int jj = tid >> 5;
    const int len = lengths[b2];
    const int hidx = (d * Bsz + b2) * Hn + j0 + jj;
    float c_reg = 0.f;
    unsigned h_bits = 0u;
    g_h[0][hidx] = 0u;

    grid_sync();   // h buffer 0 zeroed everywhere

    for (int s = 0; s < Tn; ++s) {
        const int pr = s & 1, pw_ = pr ^ 1;
        const bool act = s < len;
        const int t = d ? (len - 1 - s) : s;

        // prefetch xg early (hides DRAM latency behind mma)
        float xv0 = 0.f, xv1 = 0.f, xv2 = 0.f, xv3 = 0.f;
        if (act) {
            const float* xr = xg + (((size_t)d * Tn + t) * Bsz + b2) * G4 + j0 + jj;
            xv0 = xr[0];
            xv1 = xr[Hn];
            xv2 = xr[2 * Hn];
            xv3 = xr[3 * Hn];
        }

        // stage h (own dir, 64KB) into smem, coalesced uint4
        {
            const unsigned* hsrc = g_h[pr] + d * Bsz * Hn;
#pragma unroll
            for (int i = 0; i < 16; ++i) {
                int f = tid + i * 256;           // float4 units
                int row = f >> 7, kq = (f & 127) << 2;
                *reinterpret_cast<uint4*>(hs + row * 516 + kq) =
                    *reinterpret_cast<const uint4*>(hsrc + row * Hn + kq);
            }
        }
        __syncthreads();

        float acc[4][4];
#pragma unroll
        for (int nt = 0; nt < 4; ++nt)
#pragma unroll
            for (int i = 0; i < 4; ++i) acc[nt][i] = 0.f;

#pragma unroll
        for (int ks = 0; ks < 16; ++ks) {
            const unsigned* hp = hs + (mb * 16 + (lane >> 2)) * 516
                                 + kc * 128 + ks * 8 + (lane & 3);
            unsigned a0 = hp[0];
            unsigned a2 = hp[4];
            unsigned a1 = hp[8 * 516];
            unsigned a3 = hp[8 * 516 + 4];
#pragma unroll
            for (int nt = 0; nt < 4; ++nt)
                mma_tf32(acc[nt], a0, a1, a2, a3, wb0[ks][nt], wb1[ks][nt]);
        }

        // write K-chunk partials to smem
#pragma unroll
        for (int nt = 0; nt < 4; ++nt) {
            float* pp = part + (wid * 16 + (lane >> 2)) * 34 + nt * 8 + (lane & 3) * 2;
            *reinterpret_cast<float2*>(pp)          = make_float2(acc[nt][0], acc[nt][1]);
            *reinterpret_cast<float2*>(pp + 8 * 34) = make_float2(acc[nt][2], acc[nt][3]);
        }
        __syncthreads();

        // phase 2: reduce partials + gates (block-local)
        if (act) {
            const int m2 = b2 & 15, mo = b2 >> 4;
            float gv[4];
#pragma unroll
            for (int q = 0; q < 4; ++q) {
                float v = (q == 0) ? xv0 : (q == 1) ? xv1 : (q == 2) ? xv2 : xv3;
#pragma unroll
                for (int k2 = 0; k2 < 4; ++k2)
                    v += part[((k2 * 2 + mo) * 16 + m2) * 34 + q * 8 + jj];
                gv[q] = v;
            }
            float ig = 1.f / (1.f + __expf(-gv[0]));
            float fg = 1.f / (1.f + __expf(-gv[1]));
            float gg = tanhf(gv[2]);
            float og = 1.f / (1.f + __expf(-gv[3]));
            c_reg = fg * c_reg + ig * gg;
            float hn = og * tanhf(c_reg);
            h_bits = f2tf(hn);
            out[((size_t)b2 * Tn + t) * (2 * Hn) + d * Hn + j0 + jj] = hn;
        }
        g_h[pw_][hidx] = h_bits;   // frozen h re-written when inactive

        grid_sync();
    }
}

// ---------------- mean pooling over valid length --------------------------
__global__ void pool_kernel(const int* __restrict__ lengths,
                            float* __restrict__ out) {
    const int c = blockIdx.x * 256 + threadIdx.x;
    const int b = blockIdx.y;
    const float* p = g_out1 + (size_t)b * Tn * (2 * Hn) + c;
    float s = 0.f;
    for (int t = 0; t < Tn; ++t) s += p[(size_t)t * (2 * Hn)];
    out[b * (2 * Hn) + c] = s / (float)lengths[b];
}

// ---------------- launch ---------------------------------------------------
extern "C" void kernel_launch(void* const* d_in, const int* in_sizes, int n_in,
                              void* d_out, int out_size) {
    const float* feats = (const float*)d_in[0];
    const int*   lens  = (const int*)  d_in[1];
    const float* encW  = (const float*)d_in[2];
    const float* encb  = (const float*)d_in[3];
    const float* wih0  = (const float*)d_in[4];
    const float* whh0  = (const float*)d_in[5];
    const float* b0    = (const float*)d_in[6];
    const float* wih1  = (const float*)d_in[7];
    const float* whh1  = (const float*)d_in[8];
    const float* b1    = (const float*)d_in[9];
    float* out = (float*)d_out;

    // opt-in to >48KB dynamic smem for the recurrence kernel (not an allocation)
    cudaFuncSetAttribute(rec_kernel,
                         cudaFuncAttributeMaxDynamicSharedMemorySize, REC_SMEM);

    zero_kernel<<<2048, 256>>>();
    enc_kernel<<<Bsz * Tn, 256>>>(feats, encW, encb);

    // layer 0: project (K=256) then scan
    {
        dim3 grid(16, 128, 2);
        proj_gemm<<<grid, 256>>>(0, DENC, wih0, b0);
        rec_kernel<<<NB, 256, REC_SMEM>>>(whh0, lens, 0);
    }
    // layer 1: project (K=1024) then scan
    {
        dim3 grid(16, 128, 2);
        proj_gemm<<<grid, 256>>>(1, 2 * Hn, wih1, b1);
        rec_kernel<<<NB, 256, REC_SMEM>>>(whh1, lens, 1);
    }

    dim3 pg(4, Bsz);
    pool_kernel<<<pg, 256>>>(lens, out);
}